// round 5
// baseline (speedup 1.0000x reference)
#include <cuda_runtime.h>
#include <math.h>
#include <stdint.h>

// ---------------- problem constants ----------------
// B=32, NS=NC=1024, D=256 (Dp=257), K=128

// ---------------- scratch layout (floats) ----------------
constexpr long long SZ_Y    = 32LL * 129 * 1024;   // one complex plane
constexpr long long SZ_ZF   = 32LL * 256 * 1024;
constexpr long long SZ_BND  = 32LL * 1024 * 256;
constexpr long long SZ_L    = 32LL * 1024 * 257;
constexpr long long SZ_LBIG = 32LL * 1024 * 1024;
constexpr long long SZ_H    = 32LL * 1024 * 128;

constexpr long long OFF_YRE  = 0;
constexpr long long OFF_YIM  = OFF_YRE + SZ_Y;
constexpr long long OFF_ZF   = OFF_YIM + SZ_Y;
constexpr long long OFF_SFFT = OFF_ZF + SZ_ZF;
constexpr long long OFF_CFFT = OFF_SFFT + SZ_BND;
constexpr long long OFF_LS   = OFF_CFFT + SZ_BND;
constexpr long long OFF_LC   = OFF_LS + SZ_L;
constexpr long long OFF_LRAW = OFF_LC + SZ_L;
constexpr long long OFF_LFIX = OFF_LRAW + SZ_BND;
constexpr long long OFF_LBIG = OFF_LFIX + SZ_L;
constexpr long long OFF_XNL  = OFF_LBIG + SZ_LBIG;
constexpr long long OFF_XNC  = OFF_XNL + 32768;
constexpr long long OFF_HSA  = OFF_XNC + 32768;
constexpr long long OFF_HCA  = OFF_HSA + SZ_H;
constexpr long long OFF_MS   = OFF_HCA + SZ_H;
constexpr long long OFF_MC   = OFF_MS + SZ_H;
constexpr long long OFF_HCT  = OFF_MC + SZ_H;
constexpr long long OFF_LGS  = OFF_HCT + SZ_H;
constexpr long long OFF_LGC  = OFF_LGS + 32768;
constexpr long long TOTALF   = OFF_LGC + 32768;

__device__ float g_scratch[TOTALF];

// ---------------- device math helpers ----------------
__device__ __forceinline__ float artanh_clip(float x) {
    x = fminf(fmaxf(x, -1.f + 1e-5f), 1.f - 1e-5f);
    return 0.5f * (log1pf(x) - log1pf(-x));
}
__device__ __forceinline__ float gelu_exact(float x) {
    return 0.5f * x * (1.f + erff(x * 0.70710678118654752440f));
}

__device__ __forceinline__ float blockReduceSum(float v, float* sbuf) {
    int lane = threadIdx.x & 31, wid = threadIdx.x >> 5;
    #pragma unroll
    for (int o = 16; o; o >>= 1) v += __shfl_down_sync(0xffffffffu, v, o);
    if (lane == 0) sbuf[wid] = v;
    __syncthreads();
    int nw = (blockDim.x + 31) >> 5;
    float w = (threadIdx.x < nw) ? sbuf[threadIdx.x] : 0.f;
    if (wid == 0) {
        #pragma unroll
        for (int o = 16; o; o >>= 1) w += __shfl_down_sync(0xffffffffu, w, o);
        if (lane == 0) sbuf[32] = w;
    }
    __syncthreads();
    float r = sbuf[32];
    __syncthreads();
    return r;
}
__device__ __forceinline__ void blockReduceSum3(float& a, float& b, float& c, float* sbuf) {
    int lane = threadIdx.x & 31, wid = threadIdx.x >> 5;
    #pragma unroll
    for (int o = 16; o; o >>= 1) {
        a += __shfl_down_sync(0xffffffffu, a, o);
        b += __shfl_down_sync(0xffffffffu, b, o);
        c += __shfl_down_sync(0xffffffffu, c, o);
    }
    if (lane == 0) { sbuf[wid] = a; sbuf[34 + wid] = b; sbuf[68 + wid] = c; }
    __syncthreads();
    int nw = (blockDim.x + 31) >> 5;
    float ra = (threadIdx.x < nw) ? sbuf[threadIdx.x] : 0.f;
    float rb = (threadIdx.x < nw) ? sbuf[34 + threadIdx.x] : 0.f;
    float rc = (threadIdx.x < nw) ? sbuf[68 + threadIdx.x] : 0.f;
    if (wid == 0) {
        #pragma unroll
        for (int o = 16; o; o >>= 1) {
            ra += __shfl_down_sync(0xffffffffu, ra, o);
            rb += __shfl_down_sync(0xffffffffu, rb, o);
            rc += __shfl_down_sync(0xffffffffu, rc, o);
        }
        if (lane == 0) { sbuf[33] = ra; sbuf[67] = rb; sbuf[101] = rc; }
    }
    __syncthreads();
    a = sbuf[33]; b = sbuf[67]; c = sbuf[101];
    __syncthreads();
}
__device__ __forceinline__ float blockReduceMax(float v, float* sbuf) {
    int lane = threadIdx.x & 31, wid = threadIdx.x >> 5;
    #pragma unroll
    for (int o = 16; o; o >>= 1) v = fmaxf(v, __shfl_down_sync(0xffffffffu, v, o));
    if (lane == 0) sbuf[wid] = v;
    __syncthreads();
    int nw = (blockDim.x + 31) >> 5;
    float w = (threadIdx.x < nw) ? sbuf[threadIdx.x] : -3.4e38f;
    if (wid == 0) {
        #pragma unroll
        for (int o = 16; o; o >>= 1) w = fmaxf(w, __shfl_down_sync(0xffffffffu, w, o));
        if (lane == 0) sbuf[32] = w;
    }
    __syncthreads();
    float r = sbuf[32];
    __syncthreads();
    return r;
}

// ---------------- FFT kernels (Stockham radix-2, DIF, autosort) ----------------
template <bool LOGMAP>
__global__ void f_row256(const float* __restrict__ in,
                         float* __restrict__ yre, float* __restrict__ yim) {
    __shared__ float re[2][256], im[2][256], sred[34];
    long long row = blockIdx.x;      // b*1024 + n
    int t = threadIdx.x;             // 0..127
    float x0 = in[row * 256 + t];
    float x1 = in[row * 256 + t + 128];
    if (LOGMAP) {
        float ssq = blockReduceSum(x0 * x0 + x1 * x1, sred);
        float yn = sqrtf(fmaxf(ssq, 1e-15f));
        float f = artanh_clip(yn) / yn;
        x0 *= f; x1 *= f;
    }
    re[0][t] = x0; re[0][t + 128] = x1;
    im[0][t] = 0.f; im[0][t + 128] = 0.f;
    __syncthreads();
    int src = 0;
    #pragma unroll
    for (int s = 0; s < 8; s++) {
        int m = 1 << s, l = 128 >> s;
        int j = t >> s, k = t & (m - 1);
        float a = (float)j / (float)l, sn, cs;
        sincospif(a, &sn, &cs);      // w = cs - i*sn
        int i0 = k + j * m, i1 = i0 + l * m;
        int d0 = k + 2 * j * m, d1 = d0 + m;
        float are = re[src][i0], aim = im[src][i0];
        float bre = re[src][i1], bim = im[src][i1];
        re[src ^ 1][d0] = are + bre; im[src ^ 1][d0] = aim + bim;
        float tre = are - bre, tim = aim - bim;
        re[src ^ 1][d1] = cs * tre + sn * tim;
        im[src ^ 1][d1] = cs * tim - sn * tre;
        src ^= 1;
        __syncthreads();
    }
    int b = (int)(row >> 10), n = (int)(row & 1023);
    long long ob = ((long long)b * 129) * 1024 + n;
    yre[ob + (long long)t * 1024] = re[src][t];
    yim[ob + (long long)t * 1024] = im[src][t];
    if (t == 0) {
        yre[ob + 128LL * 1024] = re[src][128];
        yim[ob + 128LL * 1024] = im[src][128];
    }
}

__global__ void __launch_bounds__(512) f_col1024(
        const float* __restrict__ yre, const float* __restrict__ yim,
        float* __restrict__ zf) {
    __shared__ float re[2][1024], im[2][1024];
    int j = blockIdx.x, b = blockIdx.y, t = threadIdx.x;  // 512 threads
    long long ib = ((long long)b * 129 + j) * 1024;
    re[0][t] = yre[ib + t]; re[0][t + 512] = yre[ib + t + 512];
    im[0][t] = yim[ib + t]; im[0][t + 512] = yim[ib + t + 512];
    __syncthreads();
    int src = 0;
    #pragma unroll
    for (int s = 0; s < 10; s++) {
        int m = 1 << s, l = 512 >> s;
        int jj = t >> s, k = t & (m - 1);
        float a = (float)jj / (float)l, sn, cs;
        sincospif(a, &sn, &cs);
        int i0 = k + jj * m, i1 = i0 + l * m;
        int d0 = k + 2 * jj * m, d1 = d0 + m;
        float are = re[src][i0], aim = im[src][i0];
        float bre = re[src][i1], bim = im[src][i1];
        re[src ^ 1][d0] = are + bre; im[src ^ 1][d0] = aim + bim;
        float tre = are - bre, tim = aim - bim;
        re[src ^ 1][d1] = cs * tre + sn * tim;
        im[src ^ 1][d1] = cs * tim - sn * tre;
        src ^= 1;
        __syncthreads();
    }
    long long ob = ((long long)b * 256 + j) * 1024;
    zf[ob + t] = re[src][t];
    zf[ob + t + 512] = re[src][t + 512];
}

__global__ void f_mirror(float* __restrict__ zf) {
    int jp = 129 + blockIdx.x;   // 129..255
    int b = blockIdx.y;
    long long dst = ((long long)b * 256 + jp) * 1024;
    long long srcr = ((long long)b * 256 + (256 - jp)) * 1024;
    for (int k = threadIdx.x; k < 1024; k += 256) {
        int ks = (1024 - k) & 1023;
        zf[dst + k] = zf[srcr + ks];
    }
}

__global__ void f_transpose(const float* __restrict__ zf, float* __restrict__ R) {
    __shared__ float tile[32][33];
    int k0 = blockIdx.x * 32, j0 = blockIdx.y * 32, b = blockIdx.z;
    for (int r = threadIdx.y; r < 32; r += 8)
        tile[r][threadIdx.x] = zf[((long long)b * 256 + j0 + r) * 1024 + k0 + threadIdx.x];
    __syncthreads();
    for (int r = threadIdx.y; r < 32; r += 8)
        R[((long long)b * 1024 + k0 + r) * 256 + j0 + threadIdx.x] = tile[threadIdx.x][r];
}

// ---------------- 3xTF32 tensor-core GEMM (128x128x16, mma.m16n8k8) ----------------
__device__ __forceinline__ void tf32_split(float v, float& hf, float& lf) {
    uint32_t h;
    asm("cvt.rna.tf32.f32 %0, %1;" : "=r"(h) : "f"(v));
    hf = __uint_as_float(h);
    float r = v - hf;
    uint32_t l;
    asm("cvt.rna.tf32.f32 %0, %1;" : "=r"(l) : "f"(r));
    lf = __uint_as_float(l);
}
__device__ __forceinline__ void mma_tf32(float* c, const uint32_t* a, const uint32_t* b) {
    asm volatile(
        "mma.sync.aligned.m16n8k8.row.col.f32.tf32.tf32.f32 "
        "{%0,%1,%2,%3}, {%4,%5,%6,%7}, {%8,%9}, {%0,%1,%2,%3};\n"
        : "+f"(c[0]), "+f"(c[1]), "+f"(c[2]), "+f"(c[3])
        : "r"(a[0]), "r"(a[1]), "r"(a[2]), "r"(a[3]), "r"(b[0]), "r"(b[1]));
}

template <bool TA, bool TB>
__global__ void __launch_bounds__(256) gemm_tc(
        const float* __restrict__ A, const float* __restrict__ B,
        float* __restrict__ C,
        int M, int N, int K, int lda, int ldb, int ldc,
        long long sA, long long sB, long long sC) {
    __shared__ float Ah[16][132], Al[16][132], Bh[16][132], Bl[16][132];
    A += (long long)blockIdx.z * sA;
    B += (long long)blockIdx.z * sB;
    C += (long long)blockIdx.z * sC;
    int m0 = blockIdx.y * 128;
    int n0 = blockIdx.x * 128;
    int tid = threadIdx.x;
    int wid = tid >> 5, lane = tid & 31;
    int wm = (wid & 1) * 64;       // warp tile 64x32; warps 2(m) x 4(n)
    int wn = (wid >> 1) * 32;
    int l4 = lane & 3, l28 = lane >> 2;

    float acc[4][4][4];
    #pragma unroll
    for (int mi = 0; mi < 4; mi++)
        #pragma unroll
        for (int ni = 0; ni < 4; ni++)
            #pragma unroll
            for (int r = 0; r < 4; r++) acc[mi][ni][r] = 0.f;

    for (int k0 = 0; k0 < K; k0 += 16) {
        // stage A tile (128m x 16k) as hi/lo tf32
        #pragma unroll
        for (int i = 0; i < 8; i++) {
            int idx = tid + i * 256;
            int mm, kk;
            if (TA) { mm = idx & 127; kk = idx >> 7; }
            else    { kk = idx & 15;  mm = idx >> 4; }
            int m = m0 + mm, k = k0 + kk;
            float v = (m < M && k < K)
                        ? (TA ? A[(long long)k * lda + m] : A[(long long)m * lda + k])
                        : 0.f;
            float hf, lf; tf32_split(v, hf, lf);
            Ah[kk][mm] = hf; Al[kk][mm] = lf;
        }
        // stage B tile (16k x 128n)
        #pragma unroll
        for (int i = 0; i < 8; i++) {
            int idx = tid + i * 256;
            int nn, kk;
            if (TB) { kk = idx & 15;  nn = idx >> 4; }
            else    { nn = idx & 127; kk = idx >> 7; }
            int n = n0 + nn, k = k0 + kk;
            float v = (n < N && k < K)
                        ? (TB ? B[(long long)n * ldb + k] : B[(long long)k * ldb + n])
                        : 0.f;
            float hf, lf; tf32_split(v, hf, lf);
            Bh[kk][nn] = hf; Bl[kk][nn] = lf;
        }
        __syncthreads();

        #pragma unroll
        for (int kk = 0; kk < 16; kk += 8) {
            uint32_t ah[4][4], al[4][4];
            #pragma unroll
            for (int mi = 0; mi < 4; mi++) {
                int mr = wm + mi * 16 + l28;
                ah[mi][0] = __float_as_uint(Ah[kk + l4][mr]);
                ah[mi][1] = __float_as_uint(Ah[kk + l4][mr + 8]);
                ah[mi][2] = __float_as_uint(Ah[kk + l4 + 4][mr]);
                ah[mi][3] = __float_as_uint(Ah[kk + l4 + 4][mr + 8]);
                al[mi][0] = __float_as_uint(Al[kk + l4][mr]);
                al[mi][1] = __float_as_uint(Al[kk + l4][mr + 8]);
                al[mi][2] = __float_as_uint(Al[kk + l4 + 4][mr]);
                al[mi][3] = __float_as_uint(Al[kk + l4 + 4][mr + 8]);
            }
            uint32_t bh[4][2], bl[4][2];
            #pragma unroll
            for (int ni = 0; ni < 4; ni++) {
                int nc = wn + ni * 8 + l28;
                bh[ni][0] = __float_as_uint(Bh[kk + l4][nc]);
                bh[ni][1] = __float_as_uint(Bh[kk + l4 + 4][nc]);
                bl[ni][0] = __float_as_uint(Bl[kk + l4][nc]);
                bl[ni][1] = __float_as_uint(Bl[kk + l4 + 4][nc]);
            }
            #pragma unroll
            for (int mi = 0; mi < 4; mi++)
                #pragma unroll
                for (int ni = 0; ni < 4; ni++) {
                    mma_tf32(acc[mi][ni], ah[mi], bh[ni]);
                    mma_tf32(acc[mi][ni], ah[mi], bl[ni]);
                    mma_tf32(acc[mi][ni], al[mi], bh[ni]);
                }
        }
        __syncthreads();
    }

    // epilogue (all M,N here are multiples of 128 -> unguarded)
    #pragma unroll
    for (int mi = 0; mi < 4; mi++) {
        int r0 = m0 + wm + mi * 16 + l28;
        #pragma unroll
        for (int ni = 0; ni < 4; ni++) {
            int c0 = n0 + wn + ni * 8 + 2 * l4;
            C[(long long)r0 * ldc + c0] = acc[mi][ni][0];
            C[(long long)r0 * ldc + c0 + 1] = acc[mi][ni][1];
            C[(long long)(r0 + 8) * ldc + c0] = acc[mi][ni][2];
            C[(long long)(r0 + 8) * ldc + c0 + 1] = acc[mi][ni][3];
        }
    }
}

// ---------------- elementwise / reduction kernels ----------------
__global__ void k_e2l(const float* __restrict__ in, float* __restrict__ out) {
    __shared__ float sred[33];
    long long row = blockIdx.x;
    int t = threadIdx.x;
    float x = in[row * 256 + t];
    float ssq = blockReduceSum(x * x, sred);
    float xn = sqrtf(fmaxf(ssq, 1e-15f)) + 1e-5f;
    float sc = fminf(1.f, 2.0f / xn);
    x *= sc;
    float vn = sqrtf(fmaxf(ssq * sc * sc, 1e-15f));
    out[row * 257 + 1 + t] = sinhf(vn) / vn * x;
    if (t == 0) out[row * 257] = coshf(vn);
}

__global__ void k_lfix(const float* __restrict__ raw, const float* __restrict__ b,
                       float* __restrict__ out) {
    __shared__ float sred[33];
    long long row = blockIdx.x;
    int t = threadIdx.x;
    float sp = raw[row * 256 + t] + b[1 + t];
    float ssq = blockReduceSum(sp * sp, sred);
    out[row * 257 + 1 + t] = sp;
    if (t == 0) out[row * 257] = sqrtf(ssq + 1.f);
}

__global__ void k_pfix(float* __restrict__ buf, const float* __restrict__ b) {
    __shared__ float sred[33];
    long long row = blockIdx.x;
    int t = threadIdx.x;
    float sp = buf[row * 128 + t] + b[1 + t];
    float ssq = blockReduceSum(sp * sp, sred);
    buf[row * 128 + t] = sp / (sqrtf(ssq + 1.f) + 1.f);
}

__global__ void k_act(float* __restrict__ lbig, float* __restrict__ xnl) {
    __shared__ float sred[33];
    long long row = blockIdx.x;
    int t = threadIdx.x;
    float g[4];
    float ss = 0.f;
    #pragma unroll
    for (int j = 0; j < 4; j++) {
        int m = t + j * 256;
        float v = lbig[row * 1024 + m];
        float gg = gelu_exact(v);
        if (m == 0) gg = 0.f;
        g[j] = gg;
        ss += gg * gg;
    }
    float ssq = blockReduceSum(ss, sred);
    float time = sqrtf(1.f + ssq);
    #pragma unroll
    for (int j = 0; j < 4; j++) {
        int m = t + j * 256;
        lbig[row * 1024 + m] = (m == 0) ? time : g[j];
    }
    if (t == 0) xnl[row] = sqrtf(fmaxf(time * time + ssq, 1e-15f));
}

__global__ void k_colnorm(const float* __restrict__ lbig, float* __restrict__ xnc) {
    int b = blockIdx.y;
    int m = blockIdx.x * 256 + threadIdx.x;
    const float* base = lbig + (long long)b * 1024 * 1024 + m;
    float ss = 0.f;
    for (int n = 0; n < 1024; n++) {
        float v = base[(long long)n * 1024];
        ss += v * v;
    }
    xnc[b * 1024 + m] = sqrtf(fmaxf(ss, 1e-15f));
}

__global__ void k_hs(float* __restrict__ ms, const float* __restrict__ hsa,
                     const float* __restrict__ xnl, const float* __restrict__ whs,
                     float* __restrict__ lgs) {
    __shared__ float sred[102];
    long long row = blockIdx.x;
    int t = threadIdx.x;
    float v = ms[row * 128 + t];
    float mxn = sqrtf(fmaxf(blockReduceSum(v * v, sred), 1e-15f));
    float xn = xnl[row];
    float fac = tanhf(mxn / xn * artanh_clip(xn)) / mxn;
    float y = fac * v;
    float x = hsa[row * 128 + t];
    float xy = x * y, x2 = x * x, y2 = y * y;
    blockReduceSum3(xy, x2, y2, sred);
    float den = fmaxf(1.f + 2.f * xy + x2 * y2, 1e-15f);
    float h = ((1.f + 2.f * xy + y2) * x + (1.f - x2) * y) / den;
    float hn = sqrtf(fmaxf(blockReduceSum(h * h, sred), 1e-15f));
    float u = artanh_clip(hn) / hn * h;
    float g = gelu_exact(u);
    float un = sqrtf(fmaxf(blockReduceSum(g * g, sred), 1e-15f));
    float o = tanhf(un) / un * g;
    ms[row * 128 + t] = o;
    float dot = o * whs[t], on2 = o * o, dummy = 0.f;
    blockReduceSum3(dot, on2, dummy, sred);
    if (t == 0) {
        float on = sqrtf(fmaxf(on2, 1e-15f));
        float mx1 = sqrtf(fmaxf(dot * dot, 1e-15f));
        lgs[row] = tanhf(mx1 / on * artanh_clip(on)) * (dot / mx1);
    }
}

__global__ void k_hcfac(float* __restrict__ mc, const float* __restrict__ xnc) {
    __shared__ float sred[33];
    long long row = blockIdx.x;
    int t = threadIdx.x;
    float v = mc[row * 128 + t];
    float mxn = sqrtf(fmaxf(blockReduceSum(v * v, sred), 1e-15f));
    float xn = xnc[row];
    float fac = tanhf(mxn / xn * artanh_clip(xn)) / mxn;
    mc[row * 128 + t] = fac * v;
}

__global__ void k_hc(const float* __restrict__ hca, const float* __restrict__ mc,
                     float* __restrict__ hct) {
    __shared__ float sred[102];
    int b = blockIdx.y, kq = blockIdx.x;
    int t = threadIdx.x;
    float x[4], y[4];
    #pragma unroll
    for (int j = 0; j < 4; j++) {
        int m = t + j * 256;
        long long idx = ((long long)b * 1024 + m) * 128 + kq;
        x[j] = hca[idx];
        y[j] = mc[idx];
    }
    float pxy = 0.f, px2 = 0.f, py2 = 0.f;
    #pragma unroll
    for (int j = 0; j < 4; j++) { pxy += x[j] * y[j]; px2 += x[j] * x[j]; py2 += y[j] * y[j]; }
    blockReduceSum3(pxy, px2, py2, sred);
    float xy = pxy, x2 = px2, y2 = py2;
    float den = fmaxf(1.f + 2.f * xy + x2 * y2, 1e-15f);
    float h[4];
    float hs = 0.f;
    #pragma unroll
    for (int j = 0; j < 4; j++) {
        h[j] = ((1.f + 2.f * xy + y2) * x[j] + (1.f - x2) * y[j]) / den;
        hs += h[j] * h[j];
    }
    float hn = sqrtf(fmaxf(blockReduceSum(hs, sred), 1e-15f));
    float fa = artanh_clip(hn) / hn;
    float g[4];
    float gs = 0.f;
    #pragma unroll
    for (int j = 0; j < 4; j++) { g[j] = gelu_exact(fa * h[j]); gs += g[j] * g[j]; }
    float un = sqrtf(fmaxf(blockReduceSum(gs, sred), 1e-15f));
    float fb = tanhf(un) / un;
    #pragma unroll
    for (int j = 0; j < 4; j++) {
        int m = t + j * 256;
        hct[((long long)b * 128 + kq) * 1024 + m] = fb * g[j];
    }
}

__global__ void k_logc(const float* __restrict__ hct, const float* __restrict__ whc,
                       float* __restrict__ lgc) {
    int b = blockIdx.y;
    int m = blockIdx.x * 256 + threadIdx.x;
    const float* base = hct + (long long)b * 128 * 1024 + m;
    float ss = 0.f, dot = 0.f;
    #pragma unroll 4
    for (int k = 0; k < 128; k++) {
        float v = base[(long long)k * 1024];
        ss += v * v;
        dot += v * whc[k];
    }
    float xn = sqrtf(fmaxf(ss, 1e-15f));
    float mxn = sqrtf(fmaxf(dot * dot, 1e-15f));
    lgc[b * 1024 + m] = tanhf(mxn / xn * artanh_clip(xn)) * (dot / mxn);
}

__global__ void k_softmax(const float* __restrict__ in, float* __restrict__ out) {
    __shared__ float sred[33];
    int b = blockIdx.x, t = threadIdx.x;
    float v[4];
    float mx = -3.4e38f;
    #pragma unroll
    for (int j = 0; j < 4; j++) {
        v[j] = in[b * 1024 + t + j * 256];
        mx = fmaxf(mx, v[j]);
    }
    mx = blockReduceMax(mx, sred);
    float s = 0.f;
    #pragma unroll
    for (int j = 0; j < 4; j++) { v[j] = expf(v[j] - mx); s += v[j]; }
    s = blockReduceSum(s, sred);
    #pragma unroll
    for (int j = 0; j < 4; j++) out[b * 1024 + t + j * 256] = v[j] / s;
}

__global__ void k_final(const float* __restrict__ ls, const float* __restrict__ lc,
                        const float* __restrict__ as_, const float* __restrict__ ac_,
                        float* __restrict__ out) {
    __shared__ float sred[33];
    __shared__ float wsm[1024];
    __shared__ float avg[257];
    __shared__ float z[512];
    int b = blockIdx.x, t = threadIdx.x;

    #pragma unroll
    for (int j = 0; j < 4; j++) wsm[t + j * 256] = as_[b * 1024 + t + j * 256];
    __syncthreads();
    float acc = 0.f, acc2 = 0.f;
    const float* lsb = ls + (long long)b * 1024 * 257;
    for (int n = 0; n < 1024; n++) {
        float w = wsm[n];
        acc += w * lsb[n * 257 + t];
        if (t == 0) acc2 += w * lsb[n * 257 + 256];
    }
    avg[t] = acc;
    if (t == 0) avg[256] = acc2;
    __syncthreads();
    float spsum = blockReduceSum(avg[1 + t] * avg[1 + t], sred);
    float a0 = avg[0];
    float den = sqrtf(fmaxf(fabsf(-a0 * a0 + spsum), 1e-8f));
    float cs = avg[1 + t] / den;
    float c0 = a0 / den;
    float spn = sqrtf(fmaxf(blockReduceSum(cs * cs, sred), 1e-15f));
    float tt = fmaxf(c0, 1.f + 1e-7f);
    z[t] = acoshf(tt) * cs / spn;
    __syncthreads();

    #pragma unroll
    for (int j = 0; j < 4; j++) wsm[t + j * 256] = ac_[b * 1024 + t + j * 256];
    __syncthreads();
    acc = 0.f; acc2 = 0.f;
    const float* lcb = lc + (long long)b * 1024 * 257;
    for (int n = 0; n < 1024; n++) {
        float w = wsm[n];
        acc += w * lcb[n * 257 + t];
        if (t == 0) acc2 += w * lcb[n * 257 + 256];
    }
    avg[t] = acc;
    if (t == 0) avg[256] = acc2;
    __syncthreads();
    spsum = blockReduceSum(avg[1 + t] * avg[1 + t], sred);
    a0 = avg[0];
    den = sqrtf(fmaxf(fabsf(-a0 * a0 + spsum), 1e-8f));
    cs = avg[1 + t] / den;
    c0 = a0 / den;
    spn = sqrtf(fmaxf(blockReduceSum(cs * cs, sred), 1e-15f));
    tt = fmaxf(c0, 1.f + 1e-7f);
    z[256 + t] = acoshf(tt) * cs / spn;
    __syncthreads();

    float zz = z[t] * z[t] + z[256 + t] * z[256 + t];
    float vn = sqrtf(fmaxf(blockReduceSum(zz, sred), 1e-15f));
    float f = sinhf(vn) / vn;
    float* ob = out + (long long)b * 513;
    if (t == 0) ob[0] = coshf(vn);
    ob[1 + t] = f * z[t];
    ob[257 + t] = f * z[256 + t];
}

// ---------------- host-side launch helpers ----------------
static void gemm(const float* A, const float* B, float* C, int M, int N, int K,
                 int lda, int ldb, int ldc, long long sA, long long sB, long long sC,
                 int batch, bool ta, bool tb) {
    dim3 grid((N + 127) / 128, (M + 127) / 128, batch);
    if (!ta && !tb) gemm_tc<false, false><<<grid, 256>>>(A, B, C, M, N, K, lda, ldb, ldc, sA, sB, sC);
    else if (!ta && tb) gemm_tc<false, true><<<grid, 256>>>(A, B, C, M, N, K, lda, ldb, ldc, sA, sB, sC);
    else if (ta && !tb) gemm_tc<true, false><<<grid, 256>>>(A, B, C, M, N, K, lda, ldb, ldc, sA, sB, sC);
    else gemm_tc<true, true><<<grid, 256>>>(A, B, C, M, N, K, lda, ldb, ldc, sA, sB, sC);
}

extern "C" void kernel_launch(void* const* d_in, const int* in_sizes, int n_in,
                              void* d_out, int out_size) {
    const float* sent = (const float*)d_in[0];
    const float* comm = (const float*)d_in[1];
    const float* WlW  = (const float*)d_in[2];
    const float* Wlb  = (const float*)d_in[3];
    const float* WcW  = (const float*)d_in[4];
    const float* Wcb  = (const float*)d_in[5];
    const float* WsW  = (const float*)d_in[6];
    const float* Wsb  = (const float*)d_in[7];
    const float* whs  = (const float*)d_in[8];
    const float* whc  = (const float*)d_in[9];
    float* out = (float*)d_out;

    float* S = nullptr;
    cudaGetSymbolAddress((void**)&S, g_scratch);

    float* yre  = S + OFF_YRE;
    float* yim  = S + OFF_YIM;
    float* zf   = S + OFF_ZF;
    float* sfft = S + OFF_SFFT;
    float* cfft = S + OFF_CFFT;
    float* Ls   = S + OFF_LS;
    float* Lc   = S + OFF_LC;
    float* lraw = S + OFF_LRAW;
    float* lfix = S + OFF_LFIX;
    float* lbig = S + OFF_LBIG;
    float* xnl  = S + OFF_XNL;
    float* xnc  = S + OFF_XNC;
    float* hsa  = S + OFF_HSA;
    float* hca  = S + OFF_HCA;
    float* ms   = S + OFF_MS;
    float* mc   = S + OFF_MC;
    float* hct  = S + OFF_HCT;
    float* lgs  = S + OFF_LGS;
    float* lgc  = S + OFF_LGC;

    float* out_co = out;                 // (32,513)
    float* out_as = out + 32 * 513;      // (32,1024)
    float* out_ac = out_as + 32 * 1024;  // (32,1024)

    // ---- FFT (real part of fft2) via Stockham FFTs ----
    f_row256<false><<<32 * 1024, 128>>>(sent, yre, yim);
    f_col1024<<<dim3(129, 32), 512>>>(yre, yim, zf);
    f_mirror<<<dim3(127, 32), 256>>>(zf);
    f_transpose<<<dim3(32, 8, 32), dim3(32, 8)>>>(zf, sfft);
    k_e2l<<<32 * 1024, 256>>>(sfft, Ls);
    f_row256<true><<<32 * 1024, 128>>>(comm, yre, yim);
    f_col1024<<<dim3(129, 32), 512>>>(yre, yim, zf);
    f_mirror<<<dim3(127, 32), 256>>>(zf);
    f_transpose<<<dim3(32, 8, 32), dim3(32, 8)>>>(zf, cfft);
    k_e2l<<<32 * 1024, 256>>>(cfft, Lc);

    // lorentz_linear(Lc, Wl) -> lfix (space only GEMM, skip output row 0 of W)
    gemm(Lc, WlW + 257, lraw, 32 * 1024, 256, 257, 257, 257, 256, 0, 0, 0, 1, false, true);
    k_lfix<<<32 * 1024, 256>>>(lraw, Wlb, lfix);

    // einsum('bnd,bmd->bnm', Ls, lfix)
    gemm(Ls, lfix, lbig, 1024, 1024, 257, 257, 257, 1024, 1024LL * 257, 1024LL * 257, 1024LL * 1024, 32, false, true);
    k_act<<<32 * 1024, 256>>>(lbig, xnl);
    k_colnorm<<<dim3(4, 32), 256>>>(lbig, xnc);

    // Hs_a, Hc_a (poincare of lorentz_linear)
    gemm(Ls, WsW + 257, hsa, 32 * 1024, 128, 257, 257, 257, 128, 0, 0, 0, 1, false, true);
    k_pfix<<<32 * 1024, 128>>>(hsa, Wsb);
    gemm(Lc, WcW + 257, hca, 32 * 1024, 128, 257, 257, 257, 128, 0, 0, 0, 1, false, true);
    k_pfix<<<32 * 1024, 128>>>(hca, Wcb);

    // Hs path
    gemm(lbig, hca, ms, 1024, 128, 1024, 1024, 128, 128, 1024LL * 1024, 1024LL * 128, 1024LL * 128, 32, false, false);
    k_hs<<<32 * 1024, 128>>>(ms, hsa, xnl, whs, lgs);
    k_softmax<<<32, 256>>>(lgs, out_as);

    // Hc path
    gemm(lbig, hsa, mc, 1024, 128, 1024, 1024, 128, 128, 1024LL * 1024, 1024LL * 128, 1024LL * 128, 32, true, false);
    k_hcfac<<<32 * 1024, 128>>>(mc, xnc);
    k_hc<<<dim3(128, 32), 256>>>(hca, mc, hct);
    k_logc<<<dim3(4, 32), 256>>>(hct, whc, lgc);
    k_softmax<<<32, 256>>>(lgc, out_ac);

    // centroids + concat
    k_final<<<32, 256>>>(Ls, Lc, out_as, out_ac, out_co);

    (void)in_sizes; (void)n_in; (void)out_size;
}